// round 5
// baseline (speedup 1.0000x reference)
#include <cuda_runtime.h>
#include <cstdint>

// Problem constants
#define BB 8
#define TT 200
#define UU 100
#define EE 512
#define PP 640
#define HH 512
#define VV 1024
#define TUU (TT * UU)          // 20000
#define MTOT (BB * TUU)        // 160000

// Scratch for projected encoder/predictor (no cudaMalloc allowed)
__device__ float g_enc[BB * TT * HH];   // 1600 x 512
__device__ float g_pred[BB * UU * HH];  //  800 x 512

// ---------------------------------------------------------------------------
// Phase 1: generic fp32 projection  Y[M,N] = X[M,K] @ W[N,K]^T + bias
// CTA 16x16 threads, tile 64x64, 4x4 per-thread microtile, K-chunk 16.
// ---------------------------------------------------------------------------
__global__ __launch_bounds__(256) void proj_kernel(
    const float* __restrict__ X, const float* __restrict__ W,
    const float* __restrict__ bias, float* __restrict__ Y,
    int M, int N, int K)
{
    __shared__ float Xs[16][68];   // stride 68 floats = 272B (16B aligned rows)
    __shared__ float Ws[16][68];

    const int tx = threadIdx.x;          // 0..15 -> n
    const int ty = threadIdx.y;          // 0..15 -> m
    const int tid = ty * 16 + tx;
    const int mBase = blockIdx.y * 64;
    const int nBase = blockIdx.x * 64;

    const int lm = tid & 63;             // 0..63 row within tile
    const int kq = (tid >> 6) * 4;       // 0,4,8,12 k-quarter

    float acc[4][4];
#pragma unroll
    for (int i = 0; i < 4; i++)
#pragma unroll
        for (int j = 0; j < 4; j++) acc[i][j] = 0.f;

    for (int k0 = 0; k0 < K; k0 += 16) {
        // Load X tile (transposed into [k][m])
        float4 xv = make_float4(0.f, 0.f, 0.f, 0.f);
        const int row = mBase + lm;
        if (row < M)
            xv = *(const float4*)(X + (size_t)row * K + k0 + kq);
        Xs[kq + 0][lm] = xv.x;
        Xs[kq + 1][lm] = xv.y;
        Xs[kq + 2][lm] = xv.z;
        Xs[kq + 3][lm] = xv.w;

        // Load W tile (N always divisible by 64 here)
        float4 wv = *(const float4*)(W + (size_t)(nBase + lm) * K + k0 + kq);
        Ws[kq + 0][lm] = wv.x;
        Ws[kq + 1][lm] = wv.y;
        Ws[kq + 2][lm] = wv.z;
        Ws[kq + 3][lm] = wv.w;

        __syncthreads();

#pragma unroll
        for (int kk = 0; kk < 16; kk++) {
            float4 a = *(const float4*)&Xs[kk][ty * 4];
            float4 b = *(const float4*)&Ws[kk][tx * 4];
            float av[4] = {a.x, a.y, a.z, a.w};
            float bv[4] = {b.x, b.y, b.z, b.w};
#pragma unroll
            for (int i = 0; i < 4; i++)
#pragma unroll
                for (int j = 0; j < 4; j++)
                    acc[i][j] = fmaf(av[i], bv[j], acc[i][j]);
        }
        __syncthreads();
    }

    float4 bb = *(const float4*)(bias + nBase + tx * 4);
    float bv[4] = {bb.x, bb.y, bb.z, bb.w};
#pragma unroll
    for (int i = 0; i < 4; i++) {
        const int row = mBase + ty * 4 + i;
        if (row < M) {
            float4 o;
            o.x = acc[i][0] + bv[0];
            o.y = acc[i][1] + bv[1];
            o.z = acc[i][2] + bv[2];
            o.w = acc[i][3] + bv[3];
            *(float4*)(Y + (size_t)row * N + nBase + tx * 4) = o;
        }
    }
}

// ---------------------------------------------------------------------------
// Phase 2: fused joint GEMM
//   out[m, v] = 0.1 * ( relu(enc[b,t,:] + pred[b,u,:]) . W_out[v,:] + b_out[v] )
// m = b*T*U + t*U + u, flattened. CTA tile 64(M) x 256(N), K-chunk 32.
// tf32 mma.sync m16n8k8, fp32 accumulate. 8 warps = 2(M) x 4(N) warp grid,
// warp tile 32x64.
// ---------------------------------------------------------------------------
__device__ __forceinline__ unsigned f2tf32(float x)
{
    unsigned r;
    asm("cvt.rna.tf32.f32 %0, %1;" : "=r"(r) : "f"(x));
    return r;
}

__device__ __forceinline__ void mma_tf32(float* c, const unsigned* a,
                                         unsigned b0, unsigned b1)
{
    asm volatile(
        "mma.sync.aligned.m16n8k8.row.col.f32.tf32.tf32.f32 "
        "{%0,%1,%2,%3}, {%4,%5,%6,%7}, {%8,%9}, {%0,%1,%2,%3};\n"
        : "+f"(c[0]), "+f"(c[1]), "+f"(c[2]), "+f"(c[3])
        : "r"(a[0]), "r"(a[1]), "r"(a[2]), "r"(a[3]), "r"(b0), "r"(b1));
}

#define SA 36  // smem row stride (floats) for A [64 x 32] -> conflict-free frags
#define SB 36  // smem row stride (floats) for B [256 x 32] (n-major)

__global__ __launch_bounds__(256, 2) void joint_kernel(
    const float* __restrict__ Wout, const float* __restrict__ bout,
    float* __restrict__ out)
{
    __shared__ unsigned As[64 * SA];    //  9216 B
    __shared__ unsigned Bs[256 * SB];   // 36864 B
    __shared__ int encOff[64];
    __shared__ int predOff[64];

    const int tid = threadIdx.x;
    const int mBase = blockIdx.x * 64;
    const int vBase = blockIdx.y * 256;

    if (tid < 64) {
        const int gm = mBase + tid;
        const int b = gm / TUU;
        const int r = gm % TUU;
        const int t = r / UU;
        const int u = r % UU;
        encOff[tid] = (b * TT + t) * HH;
        predOff[tid] = (b * UU + u) * HH;
    }
    __syncthreads();

    const int lane = tid & 31;
    const int warp = tid >> 5;
    const int warpM = (warp & 1) * 32;      // 0 or 32
    const int warpN = (warp >> 1) * 64;     // 0,64,128,192
    const int gID = lane >> 2;              // 0..7
    const int t4 = lane & 3;                // 0..3

    // A-fill mapping: each thread covers 8 k of one m-row
    const int am = tid >> 2;                // 0..63
    const int akq = (tid & 3) * 8;          // 0,8,16,24
    const int eo = encOff[am];
    const int po = predOff[am];

    // B-fill mapping: 8 lanes per W_out row (128B coalesced), 8 passes
    const int bn = tid >> 3;                // 0..31
    const int bkk = (tid & 7) * 4;          // 0..28

    float acc[2][8][4];
#pragma unroll
    for (int mt = 0; mt < 2; mt++)
#pragma unroll
        for (int nt = 0; nt < 8; nt++)
#pragma unroll
            for (int i = 0; i < 4; i++) acc[mt][nt][i] = 0.f;

    for (int k0 = 0; k0 < HH; k0 += 32) {
        // ---- generate A chunk: relu(enc + pred), rounded to tf32 ----
        {
            float4 e0 = *(const float4*)(g_enc + eo + k0 + akq);
            float4 e1 = *(const float4*)(g_enc + eo + k0 + akq + 4);
            float4 p0 = *(const float4*)(g_pred + po + k0 + akq);
            float4 p1 = *(const float4*)(g_pred + po + k0 + akq + 4);
            uint4 v0, v1;
            v0.x = f2tf32(fmaxf(e0.x + p0.x, 0.f));
            v0.y = f2tf32(fmaxf(e0.y + p0.y, 0.f));
            v0.z = f2tf32(fmaxf(e0.z + p0.z, 0.f));
            v0.w = f2tf32(fmaxf(e0.w + p0.w, 0.f));
            v1.x = f2tf32(fmaxf(e1.x + p1.x, 0.f));
            v1.y = f2tf32(fmaxf(e1.y + p1.y, 0.f));
            v1.z = f2tf32(fmaxf(e1.z + p1.z, 0.f));
            v1.w = f2tf32(fmaxf(e1.w + p1.w, 0.f));
            *(uint4*)&As[am * SA + akq] = v0;
            *(uint4*)&As[am * SA + akq + 4] = v1;
        }
        // ---- load B chunk: W_out[vBase+n][k0..k0+31], n-major in smem ----
#pragma unroll
        for (int p = 0; p < 8; p++) {
            const int n = bn + p * 32;
            float4 w = *(const float4*)(Wout + (size_t)(vBase + n) * HH + k0 + bkk);
            uint4 wv;
            wv.x = f2tf32(w.x);
            wv.y = f2tf32(w.y);
            wv.z = f2tf32(w.z);
            wv.w = f2tf32(w.w);
            *(uint4*)&Bs[n * SB + bkk] = wv;
        }
        __syncthreads();

        // ---- 4 x k8 MMA steps ----
#pragma unroll
        for (int s = 0; s < 4; s++) {
            const int kk = s * 8;
            unsigned a[2][4];
#pragma unroll
            for (int mt = 0; mt < 2; mt++) {
                const int rb = (warpM + mt * 16 + gID) * SA + kk + t4;
                a[mt][0] = As[rb];
                a[mt][1] = As[rb + 8 * SA];
                a[mt][2] = As[rb + 4];
                a[mt][3] = As[rb + 8 * SA + 4];
            }
#pragma unroll
            for (int nt = 0; nt < 8; nt++) {
                const int nb = (warpN + nt * 8 + gID) * SB + kk + t4;
                const unsigned b0 = Bs[nb];
                const unsigned b1 = Bs[nb + 4];
                mma_tf32(acc[0][nt], a[0], b0, b1);
                mma_tf32(acc[1][nt], a[1], b0, b1);
            }
        }
        __syncthreads();
    }

    // ---- epilogue: (acc + b_out) * 0.1, fp32 out ----
#pragma unroll
    for (int mt = 0; mt < 2; mt++) {
        const int row0 = mBase + warpM + mt * 16 + gID;
#pragma unroll
        for (int nt = 0; nt < 8; nt++) {
            const int v = vBase + warpN + nt * 8 + t4 * 2;
            const float bo0 = __ldg(bout + v);
            const float bo1 = __ldg(bout + v + 1);
            float2 r0, r1;
            r0.x = (acc[mt][nt][0] + bo0) * 0.1f;
            r0.y = (acc[mt][nt][1] + bo1) * 0.1f;
            r1.x = (acc[mt][nt][2] + bo0) * 0.1f;
            r1.y = (acc[mt][nt][3] + bo1) * 0.1f;
            *(float2*)(out + (size_t)row0 * VV + v) = r0;
            *(float2*)(out + (size_t)(row0 + 8) * VV + v) = r1;
        }
    }
}

// ---------------------------------------------------------------------------
// Launch
// ---------------------------------------------------------------------------
extern "C" void kernel_launch(void* const* d_in, const int* in_sizes, int n_in,
                              void* d_out, int out_size)
{
    (void)in_sizes; (void)n_in; (void)out_size;
    const float* enc_in  = (const float*)d_in[0];  // (8,200,512)
    const float* pred_in = (const float*)d_in[1];  // (8,100,640)
    const float* W_enc   = (const float*)d_in[2];  // (512,512)
    const float* b_enc   = (const float*)d_in[3];  // (512)
    const float* W_pred  = (const float*)d_in[4];  // (512,640)
    const float* b_pred  = (const float*)d_in[5];  // (512)
    const float* W_out   = (const float*)d_in[6];  // (1024,512)
    const float* b_out   = (const float*)d_in[7];  // (1024)
    float* out = (float*)d_out;                    // (8,200,100,1024)

    void* p;
    cudaGetSymbolAddress(&p, g_enc);
    float* enc = (float*)p;
    cudaGetSymbolAddress(&p, g_pred);
    float* pred = (float*)p;

    dim3 blk(16, 16);
    // enc projection: M=1600, N=512, K=512
    proj_kernel<<<dim3(HH / 64, (BB * TT + 63) / 64), blk>>>(
        enc_in, W_enc, b_enc, enc, BB * TT, HH, EE);
    // pred projection: M=800, N=512, K=640
    proj_kernel<<<dim3(HH / 64, (BB * UU + 63) / 64), blk>>>(
        pred_in, W_pred, b_pred, pred, BB * UU, HH, PP);

    // fused joint GEMM: 2500 x 4 CTAs of 256 threads
    joint_kernel<<<dim3(MTOT / 64, VV / 256), 256>>>(W_out, b_out, out);
}